// round 16
// baseline (speedup 1.0000x reference)
#include <cuda_runtime.h>
#include <cuda_fp16.h>
#include <math.h>
#include <stdint.h>

#define B_ROWS 16384
#define D_DIM  1024
#define R_DIM  64
#define E_NUM  4
#define L_NUM  2
#define N1     256   // E * R

// ---------------------------------------------------------------------------
// Device scratch (all intermediates fp16)
// ---------------------------------------------------------------------------
__device__ __half g_W1h[L_NUM * N1 * D_DIM];   // [L][n=e*64+r][k=d]  fp16(V)
__device__ __half g_W2h[L_NUM * D_DIM * N1];   // [L][n=d][k=e*64+r]  fp16(U)
__device__ __half g_Cq [L_NUM * E_NUM * R_DIM * R_DIM];  // fp16(C), native layout
__device__ __half g_Xh [B_ROWS * D_DIM];       // fp16(x_l) after layer 0
__device__ __half g_X0h[B_ROWS * D_DIM];       // fp16(x0)
__device__ __half g_Zh [B_ROWS * N1];          // fp16(Z)
__device__ float g_Gate[B_ROWS * E_NUM];

// ---------------------------------------------------------------------------
// Helpers
// ---------------------------------------------------------------------------
__device__ __forceinline__ uint32_t smem_u32(const void* p) {
    uint32_t a;
    asm("{ .reg .u64 t; cvta.to.shared.u64 t, %1; cvt.u32.u64 %0, t; }"
        : "=r"(a) : "l"(p));
    return a;
}

#define CP_ASYNC16(dst, src) \
    asm volatile("cp.async.cg.shared.global [%0], [%1], 16;" :: "r"(dst), "l"(src))
#define CP_COMMIT() asm volatile("cp.async.commit_group;" ::: "memory")

template<int N>
__device__ __forceinline__ void cp_wait() {
    asm volatile("cp.async.wait_group %0;" :: "n"(N) : "memory");
}

#define LDSM_X4(r0, r1, r2, r3, addr) \
    asm volatile("ldmatrix.sync.aligned.m8n8.x4.shared.b16 {%0,%1,%2,%3}, [%4];" \
        : "=r"(r0), "=r"(r1), "=r"(r2), "=r"(r3) : "r"(addr))

#define MMA_F16(d, a, b0, b1) \
    asm volatile("mma.sync.aligned.m16n8k16.row.col.f32.f16.f16.f32 " \
        "{%0,%1,%2,%3}, {%4,%5,%6,%7}, {%8,%9}, {%0,%1,%2,%3};" \
        : "+f"((d)[0]), "+f"((d)[1]), "+f"((d)[2]), "+f"((d)[3]) \
        : "r"((a)[0]), "r"((a)[1]), "r"((a)[2]), "r"((a)[3]), "r"(b0), "r"(b1))

// ---------------------------------------------------------------------------
// Weight repacks (fp16)
// ---------------------------------------------------------------------------
__global__ void repack_w1_kernel(const float* __restrict__ V) {
    __shared__ float tile[64][65];
    const int blk  = blockIdx.x;
    const int dblk = blk & 15;          // D/64 = 16
    const int e    = (blk >> 4) & 3;
    const int i    = blk >> 6;
    const int tid  = threadIdx.x;

    const float* src = V + (((size_t)i * E_NUM + e) * D_DIM + dblk * 64) * R_DIM;
    #pragma unroll
    for (int it = 0; it < 16; it++) {
        int lin = tid + it * 256;
        int dr = lin >> 6, rr = lin & 63;
        tile[dr][rr] = src[dr * 64 + rr];
    }
    __syncthreads();
    __half* dst = g_W1h + ((size_t)i * N1 + e * 64) * D_DIM + dblk * 64;
    #pragma unroll
    for (int it = 0; it < 16; it++) {
        int lin = tid + it * 256;
        int rr = lin >> 6, dr = lin & 63;
        dst[(size_t)rr * D_DIM + dr] = __float2half_rn(tile[dr][rr]);
    }
}

__global__ void repack_w2_kernel(const float* __restrict__ U) {
    int idx = blockIdx.x * blockDim.x + threadIdx.x;
    if (idx >= L_NUM * D_DIM * N1) return;
    int i   = idx / (D_DIM * N1);
    int rem = idx - i * (D_DIM * N1);
    int d = rem >> 8, k2 = rem & 255;
    int e = k2 >> 6, r = k2 & 63;
    g_W2h[idx] = __float2half_rn(U[(((size_t)i * E_NUM + e) * D_DIM + d) * R_DIM + r]);
}

__global__ void repack_c_kernel(const float* __restrict__ C) {
    int idx = blockIdx.x * blockDim.x + threadIdx.x;
    if (idx < L_NUM * E_NUM * R_DIM * R_DIM)
        g_Cq[idx] = __float2half_rn(C[idx]);
}

// ---------------------------------------------------------------------------
// Gate (layer 0): one row per warp; reads fp32 x, writes gate + fp16 x copy.
// ---------------------------------------------------------------------------
__global__ void __launch_bounds__(256)
gate_f32(const float* __restrict__ X, const float* __restrict__ gateW,
         float* __restrict__ gate, __half* __restrict__ X0h)
{
    __shared__ float sG[E_NUM * D_DIM];
    const int tid = threadIdx.x;
    #pragma unroll
    for (int i = tid * 4; i < E_NUM * D_DIM; i += 1024)
        *(float4*)(sG + i) = *(const float4*)(gateW + i);
    __syncthreads();

    const int warp = tid >> 5, lane = tid & 31;
    const int b = blockIdx.x * 8 + warp;
    const float* xr = X + (size_t)b * D_DIM;
    __half* xo = X0h + (size_t)b * D_DIM;

    float a0 = 0.f, a1 = 0.f, a2 = 0.f, a3 = 0.f;
    #pragma unroll
    for (int j = 0; j < 8; j++) {
        const int off = lane * 4 + j * 128;
        float4 xv = *(const float4*)(xr + off);
        __half2 p0, p1;
        p0.x = __float2half_rn(xv.x); p0.y = __float2half_rn(xv.y);
        p1.x = __float2half_rn(xv.z); p1.y = __float2half_rn(xv.w);
        uint2 pk;
        pk.x = *(uint32_t*)&p0; pk.y = *(uint32_t*)&p1;
        *(uint2*)(xo + off) = pk;

        float4 g0 = *(const float4*)(sG + 0 * D_DIM + off);
        float4 g1 = *(const float4*)(sG + 1 * D_DIM + off);
        float4 g2 = *(const float4*)(sG + 2 * D_DIM + off);
        float4 g3 = *(const float4*)(sG + 3 * D_DIM + off);
        a0 += xv.x * g0.x + xv.y * g0.y + xv.z * g0.z + xv.w * g0.w;
        a1 += xv.x * g1.x + xv.y * g1.y + xv.z * g1.z + xv.w * g1.w;
        a2 += xv.x * g2.x + xv.y * g2.y + xv.z * g2.z + xv.w * g2.w;
        a3 += xv.x * g3.x + xv.y * g3.y + xv.z * g3.z + xv.w * g3.w;
    }
    #pragma unroll
    for (int o = 16; o > 0; o >>= 1) {
        a0 += __shfl_xor_sync(0xffffffffu, a0, o);
        a1 += __shfl_xor_sync(0xffffffffu, a1, o);
        a2 += __shfl_xor_sync(0xffffffffu, a2, o);
        a3 += __shfl_xor_sync(0xffffffffu, a3, o);
    }
    if (lane == 0) {
        float mx = fmaxf(fmaxf(a0, a1), fmaxf(a2, a3));
        float e0 = expf(a0 - mx), e1 = expf(a1 - mx);
        float e2 = expf(a2 - mx), e3 = expf(a3 - mx);
        float inv = 1.0f / (e0 + e1 + e2 + e3);
        *(float4*)(gate + (size_t)b * 4) =
            make_float4(e0 * inv, e1 * inv, e2 * inv, e3 * inv);
    }
}

// ---------------------------------------------------------------------------
// Gate (layer 1): reads fp16 x_l. 16 rows/block, warp handles 2 rows.
// ---------------------------------------------------------------------------
__global__ void __launch_bounds__(256)
gate_f16(const __half* __restrict__ Xh, const float* __restrict__ gateW,
         float* __restrict__ gate)
{
    __shared__ float sG[E_NUM * D_DIM];
    const int tid = threadIdx.x;
    #pragma unroll
    for (int i = tid * 4; i < E_NUM * D_DIM; i += 1024)
        *(float4*)(sG + i) = *(const float4*)(gateW + i);
    __syncthreads();

    const int warp = tid >> 5, lane = tid & 31;
    const int b = blockIdx.x * 16 + warp * 2;
    const __half* xr0 = Xh + (size_t)b * D_DIM;
    const __half* xr1 = xr0 + D_DIM;

    uint4 xv[2][4];
    #pragma unroll
    for (int j = 0; j < 4; j++) {
        const int off = lane * 8 + j * 256;
        xv[0][j] = *(const uint4*)(xr0 + off);
        xv[1][j] = *(const uint4*)(xr1 + off);
    }

    float acc[2][4];
    #pragma unroll
    for (int r = 0; r < 2; r++)
        #pragma unroll
        for (int e = 0; e < 4; e++) acc[r][e] = 0.0f;

    #pragma unroll
    for (int j = 0; j < 4; j++) {
        const int off = lane * 8 + j * 256;
        float2 xf[2][4];
        #pragma unroll
        for (int r = 0; r < 2; r++) {
            xf[r][0] = __half22float2(*(__half2*)&xv[r][j].x);
            xf[r][1] = __half22float2(*(__half2*)&xv[r][j].y);
            xf[r][2] = __half22float2(*(__half2*)&xv[r][j].z);
            xf[r][3] = __half22float2(*(__half2*)&xv[r][j].w);
        }
        #pragma unroll
        for (int e = 0; e < 4; e++) {
            float4 ga = *(const float4*)(sG + e * D_DIM + off);
            float4 gb = *(const float4*)(sG + e * D_DIM + off + 4);
            #pragma unroll
            for (int r = 0; r < 2; r++) {
                acc[r][e] += xf[r][0].x * ga.x + xf[r][0].y * ga.y
                           + xf[r][1].x * ga.z + xf[r][1].y * ga.w
                           + xf[r][2].x * gb.x + xf[r][2].y * gb.y
                           + xf[r][3].x * gb.z + xf[r][3].y * gb.w;
            }
        }
    }
    #pragma unroll
    for (int r = 0; r < 2; r++)
        #pragma unroll
        for (int e = 0; e < 4; e++)
            #pragma unroll
            for (int o = 16; o > 0; o >>= 1)
                acc[r][e] += __shfl_xor_sync(0xffffffffu, acc[r][e], o);

    if (lane < 2) {
        const int r = lane;
        float a0 = acc[r][0], a1 = acc[r][1], a2 = acc[r][2], a3 = acc[r][3];
        float mx = fmaxf(fmaxf(a0, a1), fmaxf(a2, a3));
        float e0 = expf(a0 - mx), e1 = expf(a1 - mx);
        float e2 = expf(a2 - mx), e3 = expf(a3 - mx);
        float inv = 1.0f / (e0 + e1 + e2 + e3);
        *(float4*)(gate + (size_t)(b + r) * 4) =
            make_float4(e0 * inv, e1 * inv, e2 * inv, e3 * inv);
    }
}

// ---------------------------------------------------------------------------
// Stage loader (256 threads): A and B each 128 rows x 32 k fp16 = 8KB.
// ---------------------------------------------------------------------------
template<int KDIM>
__device__ __forceinline__ void load_stage(
    uint32_t sbase,
    const __half* __restrict__ A, const __half* __restrict__ B,
    int k0, int tid)
{
    #pragma unroll
    for (int h = 0; h < 2; h++) {
        int c   = tid + h * 256;       // 0..511
        int row = c >> 2;
        int kb  = c & 3;
        size_t   go = (size_t)row * KDIM + k0 + kb * 8;
        uint32_t so = (uint32_t)(kb * 2048 + row * 16);
        CP_ASYNC16(sbase +         so, A + go);
        CP_ASYNC16(sbase + 8192u + so, B + go);
    }
}

// ---------------------------------------------------------------------------
// GEMM1 (fused): BM=128, BN=128, BK=32, 8 warps (4m x 2n), NST=3.
// mainloop -> tanh(H) -> smem -> per-expert K=64 mma vs C
// -> Zh = fp16(gate * tanh(.)). C staged via cp.async.
// ---------------------------------------------------------------------------
template<int KDIM, int NST>
__global__ void __launch_bounds__(256, 2)
mma_gemm1(const __half* __restrict__ Ag, const __half* __restrict__ Bg,
          const float* __restrict__ gate, const __half* __restrict__ cq,
          __half* __restrict__ outh)
{
    constexpr int BK = 32, NK = KDIM / BK;
    constexpr uint32_t STAGE = 16384u;
    constexpr uint32_t CQ_OFF = (uint32_t)NST * STAGE;
    extern __shared__ char smem[];
    const uint32_t sbase = smem_u32(smem);

    const int tid  = threadIdx.x;
    const int wid  = tid >> 5;
    const int lane = tid & 31;
    const int wm   = wid & 3;
    const int wn   = wid >> 2;

    const __half* A = Ag + (size_t)blockIdx.y * 128 * KDIM;
    const __half* B = Bg + (size_t)blockIdx.x * 128 * KDIM;

    float acc[2][8][4];
    #pragma unroll
    for (int a = 0; a < 2; a++)
        #pragma unroll
        for (int b = 0; b < 8; b++)
            #pragma unroll
            for (int c = 0; c < 4; c++) acc[a][b][c] = 0.0f;

    // stage C for this CTA's 2 experts: [e][kb 0..7][row 0..63] panels
    #pragma unroll
    for (int h = 0; h < 4; h++) {
        int lin = tid + h * 256;          // 0..1023 chunks of 16B
        int e_l = lin >> 9;
        int rem = lin & 511;
        int row = rem >> 3, kb = rem & 7;
        const __half* src = cq + ((size_t)(blockIdx.x * 2 + e_l) * 64 + row) * 64 + kb * 8;
        CP_ASYNC16(sbase + CQ_OFF + (uint32_t)(e_l * 8192 + kb * 1024 + row * 16), src);
    }
    CP_COMMIT();

    #pragma unroll
    for (int p = 0; p < NST - 1 && p < NK; p++) {
        load_stage<KDIM>(sbase + (uint32_t)p * STAGE, A, B, p * BK, tid);
        CP_COMMIT();
    }

    const uint32_t arow16 = (uint32_t)((wm * 32 + (lane & 15)) * 16);
    const uint32_t asel   = (uint32_t)(lane >> 4) * 2048u;
    const uint32_t brow16 = (uint32_t)((wn * 64 + (lane & 7) + ((lane >> 4) << 3)) * 16);
    const uint32_t bsel   = (uint32_t)((lane >> 3) & 1) * 2048u;

    for (int i = 0; i < NK; i++) {
        cp_wait<NST - 2>();
        __syncthreads();
        if (i + NST - 1 < NK) {
            load_stage<KDIM>(sbase + (uint32_t)((i + NST - 1) % NST) * STAGE,
                             A, B, (i + NST - 1) * BK, tid);
        }
        CP_COMMIT();

        const uint32_t st = sbase + (uint32_t)(i % NST) * STAGE;
        #pragma unroll
        for (int kk = 0; kk < 2; kk++) {
            const uint32_t kboff = (uint32_t)kk * 4096u;
            uint32_t ah[2][4], bb[4][4];

            #pragma unroll
            for (int g = 0; g < 4; g++) {
                uint32_t bd = st + 8192u + kboff + bsel + brow16 + (uint32_t)g * 256u;
                LDSM_X4(bb[g][0], bb[g][1], bb[g][2], bb[g][3], bd);
            }
            #pragma unroll
            for (int mt = 0; mt < 2; mt++) {
                uint32_t ad = st + kboff + asel + arow16 + (uint32_t)mt * 256u;
                LDSM_X4(ah[mt][0], ah[mt][1], ah[mt][2], ah[mt][3], ad);
            }
            #pragma unroll
            for (int mt = 0; mt < 2; mt++)
                #pragma unroll
                for (int nt = 0; nt < 8; nt++) {
                    const int g = nt >> 1, hh = (nt & 1) * 2;
                    MMA_F16(acc[mt][nt], ah[mt], bb[g][hh], bb[g][hh + 1]);
                }
        }
    }

    const int r0    = lane >> 2;
    const int cpair = (lane & 3) * 2;

    // ---- fused Z epilogue ----
    cp_wait<0>();
    __syncthreads();   // all mainloop smem reads done
    #pragma unroll
    for (int mt = 0; mt < 2; mt++)
        #pragma unroll
        for (int nt = 0; nt < 8; nt++) {
            const int col_l = wn * 64 + nt * 8 + cpair;
            const int e_l = col_l >> 6;          // == wn
            const int q   = col_l & 63;
            #pragma unroll
            for (int h = 0; h < 2; h++) {
                const int row_l = wm * 32 + mt * 16 + r0 + h * 8;
                __half2 hv;
                hv.x = __float2half_rn(tanhf(acc[mt][nt][h * 2 + 0]));
                hv.y = __float2half_rn(tanhf(acc[mt][nt][h * 2 + 1]));
                *(__half2*)(smem + e_l * 16384 + (q >> 3) * 2048
                            + row_l * 16 + (q & 7) * 2) = hv;
            }
        }
    __syncthreads();

    float zacc[2][8][4];
    #pragma unroll
    for (int a = 0; a < 2; a++)
        #pragma unroll
        for (int b = 0; b < 8; b++)
            #pragma unroll
            for (int c = 0; c < 4; c++) zacc[a][b][c] = 0.0f;

    const uint32_t HB = sbase + (uint32_t)wn * 16384u;
    const uint32_t CB = sbase + CQ_OFF + (uint32_t)wn * 8192u;
    const uint32_t zbrow16 = (uint32_t)(((lane & 7) + ((lane >> 4) << 3)) * 16);
    const uint32_t zbsel   = (uint32_t)((lane >> 3) & 1) * 1024u;

    #pragma unroll
    for (int kk = 0; kk < 4; kk++) {
        uint32_t ah[2][4], bb[4][4];
        #pragma unroll
        for (int g = 0; g < 4; g++) {
            uint32_t bd = CB + (uint32_t)(kk * 2048) + zbsel + zbrow16 + (uint32_t)g * 256u;
            LDSM_X4(bb[g][0], bb[g][1], bb[g][2], bb[g][3], bd);
        }
        #pragma unroll
        for (int mt = 0; mt < 2; mt++) {
            uint32_t ad = HB + (uint32_t)(kk * 4096) + asel + arow16 + (uint32_t)mt * 256u;
            LDSM_X4(ah[mt][0], ah[mt][1], ah[mt][2], ah[mt][3], ad);
        }
        #pragma unroll
        for (int mt = 0; mt < 2; mt++)
            #pragma unroll
            for (int nt = 0; nt < 8; nt++) {
                const int g = nt >> 1, hh = (nt & 1) * 2;
                MMA_F16(zacc[mt][nt], ah[mt], bb[g][hh], bb[g][hh + 1]);
            }
    }

    const int eg = blockIdx.x * 2 + wn;
    #pragma unroll
    for (int mt = 0; mt < 2; mt++)
        #pragma unroll
        for (int nt = 0; nt < 8; nt++) {
            const int row = blockIdx.y * 128 + wm * 32 + mt * 16 + r0;
            const int col = eg * 64 + nt * 8 + cpair;
            #pragma unroll
            for (int h = 0; h < 2; h++) {
                const int rr = row + h * 8;
                const float g = gate[(size_t)rr * 4 + eg];
                __half2 hv;
                hv.x = __float2half_rn(g * tanhf(zacc[mt][nt][h * 2 + 0]));
                hv.y = __float2half_rn(g * tanhf(zacc[mt][nt][h * 2 + 1]));
                *(__half2*)(outh + (size_t)rr * N1 + col) = hv;
            }
        }
}

// ---------------------------------------------------------------------------
// GEMM2: BM=64, BN=128, BK=32, 8 warps (2m x 4n), warp 32x32, NST=5.
// grid = (8, 256) = 2048 CTAs -> 6.92 waves (kills 13.5% wave-quant tail).
// MODE 1: out  = xlh + x0h*(A@B + bias)   (fp32 final output)
// MODE 2: outh = fp16(x0h*(1 + A@B + bias))
// ---------------------------------------------------------------------------
template<int MODE, int KDIM, int NST>
__global__ void __launch_bounds__(256, 2)
mma_gemm64(const __half* __restrict__ Ag, const __half* __restrict__ Bg,
           const __half* __restrict__ x0h, const __half* __restrict__ xlh,
           const float* __restrict__ bias,
           float* __restrict__ out, __half* __restrict__ outh, int Nstride)
{
    constexpr int BK = 32, NK = KDIM / BK;
    constexpr uint32_t STAGE = 12288u;    // 4KB A + 8KB B
    extern __shared__ char smem[];
    const uint32_t sbase = smem_u32(smem);

    const int tid  = threadIdx.x;
    const int wid  = tid >> 5;
    const int lane = tid & 31;
    const int wm   = wid & 1;            // 0..1 (32 rows each)
    const int wn   = wid >> 1;           // 0..3 (32 cols each)

    const __half* A = Ag + (size_t)blockIdx.y * 64 * KDIM;
    const __half* B = Bg + (size_t)blockIdx.x * 128 * KDIM;

    float acc[2][4][4];
    #pragma unroll
    for (int a = 0; a < 2; a++)
        #pragma unroll
        for (int b = 0; b < 4; b++)
            #pragma unroll
            for (int c = 0; c < 4; c++) acc[a][b][c] = 0.0f;

    // stage loader: A 64 rows x 4 kb (1/thread), B 128 rows x 4 kb (2/thread)
    auto load64 = [&](uint32_t sb, int k0) {
        {
            int row = tid >> 2, kb = tid & 3;
            CP_ASYNC16(sb + (uint32_t)(kb * 1024 + row * 16),
                       A + (size_t)row * KDIM + k0 + kb * 8);
        }
        #pragma unroll
        for (int h = 0; h < 2; h++) {
            int c = tid + h * 256;
            int row = c >> 2, kb = c & 3;
            CP_ASYNC16(sb + 4096u + (uint32_t)(kb * 2048 + row * 16),
                       B + (size_t)row * KDIM + k0 + kb * 8);
        }
    };

    #pragma unroll
    for (int p = 0; p < NST - 1 && p < NK; p++) {
        load64(sbase + (uint32_t)p * STAGE, p * BK);
        CP_COMMIT();
    }

    const uint32_t arow16 = (uint32_t)((wm * 32 + (lane & 15)) * 16);
    const uint32_t asel   = (uint32_t)(lane >> 4) * 1024u;   // A panel stride 1KB
    const uint32_t brow16 = (uint32_t)((wn * 32 + (lane & 7) + ((lane >> 4) << 3)) * 16);
    const uint32_t bsel   = (uint32_t)((lane >> 3) & 1) * 2048u;

    for (int i = 0; i < NK; i++) {
        cp_wait<NST - 2>();
        __syncthreads();
        if (i + NST - 1 < NK) {
            load64(sbase + (uint32_t)((i + NST - 1) % NST) * STAGE,
                   (i + NST - 1) * BK);
        }
        CP_COMMIT();

        const uint32_t st = sbase + (uint32_t)(i % NST) * STAGE;
        #pragma unroll
        for (int kk = 0; kk < 2; kk++) {
            uint32_t ah[2][4], bb[2][4];

            #pragma unroll
            for (int g = 0; g < 2; g++) {
                uint32_t bd = st + 4096u + (uint32_t)kk * 4096u + bsel + brow16
                            + (uint32_t)g * 256u;
                LDSM_X4(bb[g][0], bb[g][1], bb[g][2], bb[g][3], bd);
            }
            #pragma unroll
            for (int mt = 0; mt < 2; mt++) {
                uint32_t ad = st + (uint32_t)kk * 2048u + asel + arow16
                            + (uint32_t)mt * 256u;
                LDSM_X4(ah[mt][0], ah[mt][1], ah[mt][2], ah[mt][3], ad);
            }
            #pragma unroll
            for (int mt = 0; mt < 2; mt++)
                #pragma unroll
                for (int nt = 0; nt < 4; nt++) {
                    const int g = nt >> 1, hh = (nt & 1) * 2;
                    MMA_F16(acc[mt][nt], ah[mt], bb[g][hh], bb[g][hh + 1]);
                }
        }
    }

    const int r0    = lane >> 2;
    const int cpair = (lane & 3) * 2;
    #pragma unroll
    for (int mt = 0; mt < 2; mt++)
        #pragma unroll
        for (int nt = 0; nt < 4; nt++) {
            const int row = blockIdx.y * 64 + wm * 32 + mt * 16 + r0;
            const int col = blockIdx.x * 128 + wn * 32 + nt * 8 + cpair;
            #pragma unroll
            for (int h = 0; h < 2; h++) {
                const int rr = row + h * 8;
                const float v0 = acc[mt][nt][h * 2 + 0];
                const float v1 = acc[mt][nt][h * 2 + 1];
                const size_t o = (size_t)rr * Nstride + col;
                if (MODE == 1) {
                    const float2 bv = *(const float2*)(bias + col);
                    const float2 xf = __half22float2(*(const __half2*)(x0h + o));
                    const float2 lf = __half22float2(*(const __half2*)(xlh + o));
                    float2 ov;
                    ov.x = fmaf(xf.x, v0 + bv.x, lf.x);
                    ov.y = fmaf(xf.y, v1 + bv.y, lf.y);
                    *(float2*)(out + o) = ov;
                } else {
                    const float2 bv = *(const float2*)(bias + col);
                    const float2 xf = __half22float2(*(const __half2*)(x0h + o));
                    __half2 hv;
                    hv.x = __float2half_rn(xf.x * (1.0f + v0 + bv.x));
                    hv.y = __float2half_rn(xf.y * (1.0f + v1 + bv.y));
                    *(__half2*)(outh + o) = hv;
                }
            }
        }
}

// ---------------------------------------------------------------------------
extern "C" void kernel_launch(void* const* d_in, const int* in_sizes, int n_in,
                              void* d_out, int out_size)
{
    const float* x     = (const float*)d_in[0];
    const float* U     = (const float*)d_in[1];
    const float* V     = (const float*)d_in[2];
    const float* C     = (const float*)d_in[3];
    const float* bias  = (const float*)d_in[4];
    const float* gateW = (const float*)d_in[5];
    float* out = (float*)d_out;

    __half *w1h, *w2h, *cq, *xh, *x0h, *zh;
    float *gbuf;
    cudaGetSymbolAddress((void**)&w1h,  g_W1h);
    cudaGetSymbolAddress((void**)&w2h,  g_W2h);
    cudaGetSymbolAddress((void**)&cq,   g_Cq);
    cudaGetSymbolAddress((void**)&xh,   g_Xh);
    cudaGetSymbolAddress((void**)&x0h,  g_X0h);
    cudaGetSymbolAddress((void**)&zh,   g_Zh);
    cudaGetSymbolAddress((void**)&gbuf, g_Gate);

    const int G1_SMEM = 3 * 16384 + 16384;   // 64 KB (3 stages + C)
    const int G2_SMEM = 5 * 12288;           // 60 KB
    cudaFuncSetAttribute((const void*)mma_gemm1<1024, 3>,
                         cudaFuncAttributeMaxDynamicSharedMemorySize, G1_SMEM);
    cudaFuncSetAttribute((const void*)mma_gemm64<1, 256, 5>,
                         cudaFuncAttributeMaxDynamicSharedMemorySize, G2_SMEM);
    cudaFuncSetAttribute((const void*)mma_gemm64<2, 256, 5>,
                         cudaFuncAttributeMaxDynamicSharedMemorySize, G2_SMEM);

    repack_w1_kernel<<<L_NUM * E_NUM * (D_DIM / 64), 256>>>(V);
    repack_w2_kernel<<<(L_NUM * D_DIM * N1 + 255) / 256, 256>>>(U);
    repack_c_kernel<<<(L_NUM * E_NUM * R_DIM * R_DIM + 255) / 256, 256>>>(C);

    for (int i = 0; i < L_NUM; i++) {
        const size_t woff = (size_t)i * N1 * D_DIM;
        const __half* cql = cq + (size_t)i * E_NUM * R_DIM * R_DIM;
        const __half* xin = (i == 0) ? x0h : xh;

        // gate (layer 0 also emits x0h)
        if (i == 0)
            gate_f32<<<B_ROWS / 8, 256>>>(x, gateW, gbuf, x0h);
        else
            gate_f16<<<B_ROWS / 16, 256>>>(xh, gateW, gbuf);

        // GEMM1 fused: Zh = fp16(gate * tanh(C @ tanh(Xin @ W1^T)))
        mma_gemm1<1024, 3><<<dim3(2, B_ROWS / 128), 256, G1_SMEM>>>(
            xin, w1h + woff, gbuf, cql, zh);

        // GEMM2  [16384 x 1024], K = 256, BM=64 (anti wave-quantization)
        if (i == 0) {
            mma_gemm64<2, 256, 5><<<dim3(8, B_ROWS / 64), 256, G2_SMEM>>>(
                zh, w2h + woff, x0h, nullptr, bias, nullptr, xh, D_DIM);
        } else {
            mma_gemm64<1, 256, 5><<<dim3(8, B_ROWS / 64), 256, G2_SMEM>>>(
                zh, w2h + woff, x0h, xh, bias + (size_t)i * D_DIM, out, nullptr, D_DIM);
        }
    }
}

// round 17
// speedup vs baseline: 1.1161x; 1.1161x over previous
#include <cuda_runtime.h>
#include <cuda_fp16.h>
#include <math.h>
#include <stdint.h>

#define B_ROWS 16384
#define D_DIM  1024
#define R_DIM  64
#define E_NUM  4
#define L_NUM  2
#define N1     256   // E * R

// ---------------------------------------------------------------------------
// Device scratch (all intermediates fp16)
// ---------------------------------------------------------------------------
__device__ __half g_W1h[L_NUM * N1 * D_DIM];   // [L][n=e*64+r][k=d]  fp16(V)
__device__ __half g_W2h[L_NUM * D_DIM * N1];   // [L][n=d][k=e*64+r]  fp16(U)
__device__ __half g_Cq [L_NUM * E_NUM * R_DIM * R_DIM];  // fp16(C), native layout
__device__ __half g_Xh [B_ROWS * D_DIM];       // fp16(x_l) after layer 0
__device__ __half g_X0h[B_ROWS * D_DIM];       // fp16(x0)
__device__ __half g_Zh [B_ROWS * N1];          // fp16(Z)
__device__ float g_Gate[B_ROWS * E_NUM];

// ---------------------------------------------------------------------------
// Helpers
// ---------------------------------------------------------------------------
__device__ __forceinline__ uint32_t smem_u32(const void* p) {
    uint32_t a;
    asm("{ .reg .u64 t; cvta.to.shared.u64 t, %1; cvt.u32.u64 %0, t; }"
        : "=r"(a) : "l"(p));
    return a;
}

#define CP_ASYNC16(dst, src) \
    asm volatile("cp.async.cg.shared.global [%0], [%1], 16;" :: "r"(dst), "l"(src))
#define CP_COMMIT() asm volatile("cp.async.commit_group;" ::: "memory")

template<int N>
__device__ __forceinline__ void cp_wait() {
    asm volatile("cp.async.wait_group %0;" :: "n"(N) : "memory");
}

#define LDSM_X4(r0, r1, r2, r3, addr) \
    asm volatile("ldmatrix.sync.aligned.m8n8.x4.shared.b16 {%0,%1,%2,%3}, [%4];" \
        : "=r"(r0), "=r"(r1), "=r"(r2), "=r"(r3) : "r"(addr))

#define MMA_F16(d, a, b0, b1) \
    asm volatile("mma.sync.aligned.m16n8k16.row.col.f32.f16.f16.f32 " \
        "{%0,%1,%2,%3}, {%4,%5,%6,%7}, {%8,%9}, {%0,%1,%2,%3};" \
        : "+f"((d)[0]), "+f"((d)[1]), "+f"((d)[2]), "+f"((d)[3]) \
        : "r"((a)[0]), "r"((a)[1]), "r"((a)[2]), "r"((a)[3]), "r"(b0), "r"(b1))

// ---------------------------------------------------------------------------
// Unified weight repack (one launch):
//   blocks [0, 128)    : W1 via 64x64 smem transpose
//   blocks [128, 144)  : W2 coalesced convert (flat)
//   block  144         : C convert
// ---------------------------------------------------------------------------
__global__ void __launch_bounds__(256)
repack_all_kernel(const float* __restrict__ V, const float* __restrict__ U,
                  const float* __restrict__ C)
{
    const int blk = blockIdx.x;
    const int tid = threadIdx.x;

    if (blk < 128) {
        // ---- W1[i][n=e*64+r][k=d] = V[i,e,d,r], transposed through smem ----
        __shared__ float tile[64][65];
        const int dblk = blk & 15;          // D/64 = 16
        const int e    = (blk >> 4) & 3;
        const int i    = blk >> 6;

        const float* src = V + (((size_t)i * E_NUM + e) * D_DIM + dblk * 64) * R_DIM;
        #pragma unroll
        for (int it = 0; it < 16; it++) {
            int lin = tid + it * 256;
            int dr = lin >> 6, rr = lin & 63;
            tile[dr][rr] = src[dr * 64 + rr];
        }
        __syncthreads();
        __half* dst = g_W1h + ((size_t)i * N1 + e * 64) * D_DIM + dblk * 64;
        #pragma unroll
        for (int it = 0; it < 16; it++) {
            int lin = tid + it * 256;
            int rr = lin >> 6, dr = lin & 63;
            dst[(size_t)rr * D_DIM + dr] = __float2half_rn(tile[dr][rr]);
        }
    } else if (blk < 144) {
        // ---- W2[i][d][k2=e*64+r] = U[i,e,d,r] ----
        const int sub = blk - 128;          // 0..15
        #pragma unroll
        for (int it = 0; it < 128; it++) {
            int idx = (sub * 128 + it) * 256 + tid;   // covers 2*1024*256 = 524288
            int i   = idx / (D_DIM * N1);
            int rem = idx - i * (D_DIM * N1);
            int d = rem >> 8, k2 = rem & 255;
            int e = k2 >> 6, r = k2 & 63;
            g_W2h[idx] = __float2half_rn(
                U[(((size_t)i * E_NUM + e) * D_DIM + d) * R_DIM + r]);
        }
    } else {
        // ---- C convert: 2*4*64*64 = 32768 elems ----
        #pragma unroll
        for (int it = 0; it < 128; it++) {
            int idx = it * 256 + tid;
            g_Cq[idx] = __float2half_rn(C[idx]);
        }
    }
}

// ---------------------------------------------------------------------------
// Gate (layer 0): one row per warp; reads fp32 x, writes gate + fp16 x copy.
// ---------------------------------------------------------------------------
__global__ void __launch_bounds__(256)
gate_f32(const float* __restrict__ X, const float* __restrict__ gateW,
         float* __restrict__ gate, __half* __restrict__ X0h)
{
    __shared__ float sG[E_NUM * D_DIM];
    const int tid = threadIdx.x;
    #pragma unroll
    for (int i = tid * 4; i < E_NUM * D_DIM; i += 1024)
        *(float4*)(sG + i) = *(const float4*)(gateW + i);
    __syncthreads();

    const int warp = tid >> 5, lane = tid & 31;
    const int b = blockIdx.x * 8 + warp;
    const float* xr = X + (size_t)b * D_DIM;
    __half* xo = X0h + (size_t)b * D_DIM;

    float a0 = 0.f, a1 = 0.f, a2 = 0.f, a3 = 0.f;
    #pragma unroll
    for (int j = 0; j < 8; j++) {
        const int off = lane * 4 + j * 128;
        float4 xv = *(const float4*)(xr + off);
        __half2 p0, p1;
        p0.x = __float2half_rn(xv.x); p0.y = __float2half_rn(xv.y);
        p1.x = __float2half_rn(xv.z); p1.y = __float2half_rn(xv.w);
        uint2 pk;
        pk.x = *(uint32_t*)&p0; pk.y = *(uint32_t*)&p1;
        *(uint2*)(xo + off) = pk;

        float4 g0 = *(const float4*)(sG + 0 * D_DIM + off);
        float4 g1 = *(const float4*)(sG + 1 * D_DIM + off);
        float4 g2 = *(const float4*)(sG + 2 * D_DIM + off);
        float4 g3 = *(const float4*)(sG + 3 * D_DIM + off);
        a0 += xv.x * g0.x + xv.y * g0.y + xv.z * g0.z + xv.w * g0.w;
        a1 += xv.x * g1.x + xv.y * g1.y + xv.z * g1.z + xv.w * g1.w;
        a2 += xv.x * g2.x + xv.y * g2.y + xv.z * g2.z + xv.w * g2.w;
        a3 += xv.x * g3.x + xv.y * g3.y + xv.z * g3.z + xv.w * g3.w;
    }
    #pragma unroll
    for (int o = 16; o > 0; o >>= 1) {
        a0 += __shfl_xor_sync(0xffffffffu, a0, o);
        a1 += __shfl_xor_sync(0xffffffffu, a1, o);
        a2 += __shfl_xor_sync(0xffffffffu, a2, o);
        a3 += __shfl_xor_sync(0xffffffffu, a3, o);
    }
    if (lane == 0) {
        float mx = fmaxf(fmaxf(a0, a1), fmaxf(a2, a3));
        float e0 = expf(a0 - mx), e1 = expf(a1 - mx);
        float e2 = expf(a2 - mx), e3 = expf(a3 - mx);
        float inv = 1.0f / (e0 + e1 + e2 + e3);
        *(float4*)(gate + (size_t)b * 4) =
            make_float4(e0 * inv, e1 * inv, e2 * inv, e3 * inv);
    }
}

// ---------------------------------------------------------------------------
// Gate (layer 1): reads fp16 x_l. 16 rows/block, warp handles 2 rows.
// ---------------------------------------------------------------------------
__global__ void __launch_bounds__(256)
gate_f16(const __half* __restrict__ Xh, const float* __restrict__ gateW,
         float* __restrict__ gate)
{
    __shared__ float sG[E_NUM * D_DIM];
    const int tid = threadIdx.x;
    #pragma unroll
    for (int i = tid * 4; i < E_NUM * D_DIM; i += 1024)
        *(float4*)(sG + i) = *(const float4*)(gateW + i);
    __syncthreads();

    const int warp = tid >> 5, lane = tid & 31;
    const int b = blockIdx.x * 16 + warp * 2;
    const __half* xr0 = Xh + (size_t)b * D_DIM;
    const __half* xr1 = xr0 + D_DIM;

    uint4 xv[2][4];
    #pragma unroll
    for (int j = 0; j < 4; j++) {
        const int off = lane * 8 + j * 256;
        xv[0][j] = *(const uint4*)(xr0 + off);
        xv[1][j] = *(const uint4*)(xr1 + off);
    }

    float acc[2][4];
    #pragma unroll
    for (int r = 0; r < 2; r++)
        #pragma unroll
        for (int e = 0; e < 4; e++) acc[r][e] = 0.0f;

    #pragma unroll
    for (int j = 0; j < 4; j++) {
        const int off = lane * 8 + j * 256;
        float2 xf[2][4];
        #pragma unroll
        for (int r = 0; r < 2; r++) {
            xf[r][0] = __half22float2(*(__half2*)&xv[r][j].x);
            xf[r][1] = __half22float2(*(__half2*)&xv[r][j].y);
            xf[r][2] = __half22float2(*(__half2*)&xv[r][j].z);
            xf[r][3] = __half22float2(*(__half2*)&xv[r][j].w);
        }
        #pragma unroll
        for (int e = 0; e < 4; e++) {
            float4 ga = *(const float4*)(sG + e * D_DIM + off);
            float4 gb = *(const float4*)(sG + e * D_DIM + off + 4);
            #pragma unroll
            for (int r = 0; r < 2; r++) {
                acc[r][e] += xf[r][0].x * ga.x + xf[r][0].y * ga.y
                           + xf[r][1].x * ga.z + xf[r][1].y * ga.w
                           + xf[r][2].x * gb.x + xf[r][2].y * gb.y
                           + xf[r][3].x * gb.z + xf[r][3].y * gb.w;
            }
        }
    }
    #pragma unroll
    for (int r = 0; r < 2; r++)
        #pragma unroll
        for (int e = 0; e < 4; e++)
            #pragma unroll
            for (int o = 16; o > 0; o >>= 1)
                acc[r][e] += __shfl_xor_sync(0xffffffffu, acc[r][e], o);

    if (lane < 2) {
        const int r = lane;
        float a0 = acc[r][0], a1 = acc[r][1], a2 = acc[r][2], a3 = acc[r][3];
        float mx = fmaxf(fmaxf(a0, a1), fmaxf(a2, a3));
        float e0 = expf(a0 - mx), e1 = expf(a1 - mx);
        float e2 = expf(a2 - mx), e3 = expf(a3 - mx);
        float inv = 1.0f / (e0 + e1 + e2 + e3);
        *(float4*)(gate + (size_t)(b + r) * 4) =
            make_float4(e0 * inv, e1 * inv, e2 * inv, e3 * inv);
    }
}

// ---------------------------------------------------------------------------
// Stage loader (256 threads): A and B each 128 rows x 32 k fp16 = 8KB.
// ---------------------------------------------------------------------------
template<int KDIM>
__device__ __forceinline__ void load_stage(
    uint32_t sbase,
    const __half* __restrict__ A, const __half* __restrict__ B,
    int k0, int tid)
{
    #pragma unroll
    for (int h = 0; h < 2; h++) {
        int c   = tid + h * 256;       // 0..511
        int row = c >> 2;
        int kb  = c & 3;
        size_t   go = (size_t)row * KDIM + k0 + kb * 8;
        uint32_t so = (uint32_t)(kb * 2048 + row * 16);
        CP_ASYNC16(sbase +         so, A + go);
        CP_ASYNC16(sbase + 8192u + so, B + go);
    }
}

// ---------------------------------------------------------------------------
// fp16 mma GEMM: BM=128, BN=128, BK=32, 8 warps (4m x 2n)  [round-14 best].
// MODE 0 (NST=3): GEMM1 fused — tanh(H) -> smem -> per-expert K=64 mma vs C
//                 -> Zh = fp16(gate * tanh(.)). C staged via cp.async.
// MODE 1 (NST=5): out  = xlh + x0h*(A@B + bias)   (fp32 final output)
// MODE 2 (NST=5): outh = fp16(x0h*(1 + A@B + bias))
// ---------------------------------------------------------------------------
template<int MODE, int KDIM, int NST>
__global__ void __launch_bounds__(256, 2)
mma_gemm(const __half* __restrict__ Ag, const __half* __restrict__ Bg,
         const __half* __restrict__ x0h, const __half* __restrict__ xlh,
         const float* __restrict__ bias, const float* __restrict__ gate,
         const __half* __restrict__ cq,
         float* __restrict__ out, __half* __restrict__ outh, int Nstride)
{
    constexpr int BK = 32, NK = KDIM / BK;
    constexpr uint32_t STAGE = 16384u;
    constexpr uint32_t CQ_OFF = (uint32_t)NST * STAGE;
    extern __shared__ char smem[];
    const uint32_t sbase = smem_u32(smem);

    const int tid  = threadIdx.x;
    const int wid  = tid >> 5;
    const int lane = tid & 31;
    const int wm   = wid & 3;
    const int wn   = wid >> 2;

    const __half* A = Ag + (size_t)blockIdx.y * 128 * KDIM;
    const __half* B = Bg + (size_t)blockIdx.x * 128 * KDIM;

    float acc[2][8][4];
    #pragma unroll
    for (int a = 0; a < 2; a++)
        #pragma unroll
        for (int b = 0; b < 8; b++)
            #pragma unroll
            for (int c = 0; c < 4; c++) acc[a][b][c] = 0.0f;

    if (MODE == 0) {
        // stage C for this CTA's 2 experts: [e][kb 0..7][row 0..63] panels
        #pragma unroll
        for (int h = 0; h < 4; h++) {
            int lin = tid + h * 256;          // 0..1023 chunks of 16B
            int e_l = lin >> 9;
            int rem = lin & 511;
            int row = rem >> 3, kb = rem & 7;
            const __half* src = cq + ((size_t)(blockIdx.x * 2 + e_l) * 64 + row) * 64 + kb * 8;
            CP_ASYNC16(sbase + CQ_OFF + (uint32_t)(e_l * 8192 + kb * 1024 + row * 16), src);
        }
        CP_COMMIT();
    }

    #pragma unroll
    for (int p = 0; p < NST - 1 && p < NK; p++) {
        load_stage<KDIM>(sbase + (uint32_t)p * STAGE, A, B, p * BK, tid);
        CP_COMMIT();
    }

    const uint32_t arow16 = (uint32_t)((wm * 32 + (lane & 15)) * 16);
    const uint32_t asel   = (uint32_t)(lane >> 4) * 2048u;
    const uint32_t brow16 = (uint32_t)((wn * 64 + (lane & 7) + ((lane >> 4) << 3)) * 16);
    const uint32_t bsel   = (uint32_t)((lane >> 3) & 1) * 2048u;

    for (int i = 0; i < NK; i++) {
        cp_wait<NST - 2>();
        __syncthreads();
        if (i + NST - 1 < NK) {
            load_stage<KDIM>(sbase + (uint32_t)((i + NST - 1) % NST) * STAGE,
                             A, B, (i + NST - 1) * BK, tid);
        }
        CP_COMMIT();

        const uint32_t st = sbase + (uint32_t)(i % NST) * STAGE;
        #pragma unroll
        for (int kk = 0; kk < 2; kk++) {
            const uint32_t kboff = (uint32_t)kk * 4096u;
            uint32_t ah[2][4], bb[4][4];

            #pragma unroll
            for (int g = 0; g < 4; g++) {
                uint32_t bd = st + 8192u + kboff + bsel + brow16 + (uint32_t)g * 256u;
                LDSM_X4(bb[g][0], bb[g][1], bb[g][2], bb[g][3], bd);
            }
            #pragma unroll
            for (int mt = 0; mt < 2; mt++) {
                uint32_t ad = st + kboff + asel + arow16 + (uint32_t)mt * 256u;
                LDSM_X4(ah[mt][0], ah[mt][1], ah[mt][2], ah[mt][3], ad);
            }
            #pragma unroll
            for (int mt = 0; mt < 2; mt++)
                #pragma unroll
                for (int nt = 0; nt < 8; nt++) {
                    const int g = nt >> 1, hh = (nt & 1) * 2;
                    MMA_F16(acc[mt][nt], ah[mt], bb[g][hh], bb[g][hh + 1]);
                }
        }
    }

    const int r0    = lane >> 2;
    const int cpair = (lane & 3) * 2;

    if (MODE == 0) {
        // ---- fused Z epilogue ----
        cp_wait<0>();
        __syncthreads();   // all mainloop smem reads done
        #pragma unroll
        for (int mt = 0; mt < 2; mt++)
            #pragma unroll
            for (int nt = 0; nt < 8; nt++) {
                const int col_l = wn * 64 + nt * 8 + cpair;
                const int e_l = col_l >> 6;          // == wn
                const int q   = col_l & 63;
                #pragma unroll
                for (int h = 0; h < 2; h++) {
                    const int row_l = wm * 32 + mt * 16 + r0 + h * 8;
                    __half2 hv;
                    hv.x = __float2half_rn(tanhf(acc[mt][nt][h * 2 + 0]));
                    hv.y = __float2half_rn(tanhf(acc[mt][nt][h * 2 + 1]));
                    *(__half2*)(smem + e_l * 16384 + (q >> 3) * 2048
                                + row_l * 16 + (q & 7) * 2) = hv;
                }
            }
        __syncthreads();

        float zacc[2][8][4];
        #pragma unroll
        for (int a = 0; a < 2; a++)
            #pragma unroll
            for (int b = 0; b < 8; b++)
                #pragma unroll
                for (int c = 0; c < 4; c++) zacc[a][b][c] = 0.0f;

        const uint32_t HB = sbase + (uint32_t)wn * 16384u;
        const uint32_t CB = sbase + CQ_OFF + (uint32_t)wn * 8192u;
        const uint32_t zbrow16 = (uint32_t)(((lane & 7) + ((lane >> 4) << 3)) * 16);
        const uint32_t zbsel   = (uint32_t)((lane >> 3) & 1) * 1024u;

        #pragma unroll
        for (int kk = 0; kk < 4; kk++) {
            uint32_t ah[2][4], bb[4][4];
            #pragma unroll
            for (int g = 0; g < 4; g++) {
                uint32_t bd = CB + (uint32_t)(kk * 2048) + zbsel + zbrow16 + (uint32_t)g * 256u;
                LDSM_X4(bb[g][0], bb[g][1], bb[g][2], bb[g][3], bd);
            }
            #pragma unroll
            for (int mt = 0; mt < 2; mt++) {
                uint32_t ad = HB + (uint32_t)(kk * 4096) + asel + arow16 + (uint32_t)mt * 256u;
                LDSM_X4(ah[mt][0], ah[mt][1], ah[mt][2], ah[mt][3], ad);
            }
            #pragma unroll
            for (int mt = 0; mt < 2; mt++)
                #pragma unroll
                for (int nt = 0; nt < 8; nt++) {
                    const int g = nt >> 1, hh = (nt & 1) * 2;
                    MMA_F16(zacc[mt][nt], ah[mt], bb[g][hh], bb[g][hh + 1]);
                }
        }

        const int eg = blockIdx.x * 2 + wn;
        #pragma unroll
        for (int mt = 0; mt < 2; mt++)
            #pragma unroll
            for (int nt = 0; nt < 8; nt++) {
                const int row = blockIdx.y * 128 + wm * 32 + mt * 16 + r0;
                const int col = eg * 64 + nt * 8 + cpair;
                #pragma unroll
                for (int h = 0; h < 2; h++) {
                    const int rr = row + h * 8;
                    const float g = gate[(size_t)rr * 4 + eg];
                    __half2 hv;
                    hv.x = __float2half_rn(g * tanhf(zacc[mt][nt][h * 2 + 0]));
                    hv.y = __float2half_rn(g * tanhf(zacc[mt][nt][h * 2 + 1]));
                    *(__half2*)(outh + (size_t)rr * N1 + col) = hv;
                }
            }
    } else {
        #pragma unroll
        for (int mt = 0; mt < 2; mt++)
            #pragma unroll
            for (int nt = 0; nt < 8; nt++) {
                const int row = blockIdx.y * 128 + wm * 32 + mt * 16 + r0;
                const int col = blockIdx.x * 128 + wn * 64 + nt * 8 + cpair;
                #pragma unroll
                for (int h = 0; h < 2; h++) {
                    const int rr = row + h * 8;
                    const float v0 = acc[mt][nt][h * 2 + 0];
                    const float v1 = acc[mt][nt][h * 2 + 1];
                    const size_t o = (size_t)rr * Nstride + col;
                    if (MODE == 1) {
                        const float2 bv = *(const float2*)(bias + col);
                        const float2 xf = __half22float2(*(const __half2*)(x0h + o));
                        const float2 lf = __half22float2(*(const __half2*)(xlh + o));
                        float2 ov;
                        ov.x = fmaf(xf.x, v0 + bv.x, lf.x);
                        ov.y = fmaf(xf.y, v1 + bv.y, lf.y);
                        *(float2*)(out + o) = ov;
                    } else {
                        const float2 bv = *(const float2*)(bias + col);
                        const float2 xf = __half22float2(*(const __half2*)(x0h + o));
                        __half2 hv;
                        hv.x = __float2half_rn(xf.x * (1.0f + v0 + bv.x));
                        hv.y = __float2half_rn(xf.y * (1.0f + v1 + bv.y));
                        *(__half2*)(outh + o) = hv;
                    }
                }
            }
    }
}

// ---------------------------------------------------------------------------
extern "C" void kernel_launch(void* const* d_in, const int* in_sizes, int n_in,
                              void* d_out, int out_size)
{
    const float* x     = (const float*)d_in[0];
    const float* U     = (const float*)d_in[1];
    const float* V     = (const float*)d_in[2];
    const float* C     = (const float*)d_in[3];
    const float* bias  = (const float*)d_in[4];
    const float* gateW = (const float*)d_in[5];
    float* out = (float*)d_out;

    __half *w1h, *w2h, *cq, *xh, *x0h, *zh;
    float *gbuf;
    cudaGetSymbolAddress((void**)&w1h,  g_W1h);
    cudaGetSymbolAddress((void**)&w2h,  g_W2h);
    cudaGetSymbolAddress((void**)&cq,   g_Cq);
    cudaGetSymbolAddress((void**)&xh,   g_Xh);
    cudaGetSymbolAddress((void**)&x0h,  g_X0h);
    cudaGetSymbolAddress((void**)&zh,   g_Zh);
    cudaGetSymbolAddress((void**)&gbuf, g_Gate);

    const int G1_SMEM = 3 * 16384 + 16384;   // 64 KB (3 stages + C)
    const int G2_SMEM = 5 * 16384;           // 80 KB
    cudaFuncSetAttribute((const void*)mma_gemm<0, 1024, 3>,
                         cudaFuncAttributeMaxDynamicSharedMemorySize, G1_SMEM);
    cudaFuncSetAttribute((const void*)mma_gemm<1, 256, 5>,
                         cudaFuncAttributeMaxDynamicSharedMemorySize, G2_SMEM);
    cudaFuncSetAttribute((const void*)mma_gemm<2, 256, 5>,
                         cudaFuncAttributeMaxDynamicSharedMemorySize, G2_SMEM);

    repack_all_kernel<<<145, 256>>>(V, U, C);

    for (int i = 0; i < L_NUM; i++) {
        const size_t woff = (size_t)i * N1 * D_DIM;
        const __half* cql = cq + (size_t)i * E_NUM * R_DIM * R_DIM;
        const __half* xin = (i == 0) ? x0h : xh;

        // gate (layer 0 also emits x0h)
        if (i == 0)
            gate_f32<<<B_ROWS / 8, 256>>>(x, gateW, gbuf, x0h);
        else
            gate_f16<<<B_ROWS / 16, 256>>>(xh, gateW, gbuf);

        // GEMM1 fused: Zh = fp16(gate * tanh(C @ tanh(Xin @ W1^T)))
        mma_gemm<0, 1024, 3><<<dim3(2, B_ROWS / 128), 256, G1_SMEM>>>(
            xin, w1h + woff, nullptr, nullptr, nullptr, gbuf, cql,
            nullptr, zh, N1);

        // GEMM2  [16384 x 1024], K = 256
        if (i == 0) {
            mma_gemm<2, 256, 5><<<dim3(8, B_ROWS / 128), 256, G2_SMEM>>>(
                zh, w2h + woff, x0h, nullptr, bias, nullptr, nullptr,
                nullptr, xh, D_DIM);
        } else {
            mma_gemm<1, 256, 5><<<dim3(8, B_ROWS / 128), 256, G2_SMEM>>>(
                zh, w2h + woff, x0h, xh, bias + (size_t)i * D_DIM, nullptr, nullptr,
                out, nullptr, D_DIM);
        }
    }
}